// round 7
// baseline (speedup 1.0000x reference)
#include <cuda_runtime.h>
#include <cuda_bf16.h>
#include <stdint.h>

// cdist: out[i,j] = sqrt(max(||xi||^2 + ||xj||^2 - 2*dot(xi,xj), 0))
// dot via bf16 hi/lo split on mma.sync: dot ~= hiA.hiB + hiA.loB + loA.hiB.
// R7: prep kernel materializes per-lane MMA *fragments* (built with the exact
// R4 ldmatrix path) into global images; main kernel is barrier-free:
// LDG.128 fragments -> HMMA -> STG.128. No smem, no ldmatrix, no syncthreads.

#define NPTS 16384
#define NT   (NPTS / 128)   // 128 tiles per dimension

// Fragment images (uint4 = one ldmatrix.x4 result = 4 regs)
// A: [tile][wr(2)][lane(32)][16]  : ks0{ah0..3, al0..3} ks1{...}
// B: [tile][wc(4)][lane(32)][8]   : ks0{bh0,bh1,bl0,bl1} ks1{...}
__device__ __align__(128) uint4 AfragImg[(size_t)NT * 2 * 32 * 16];
__device__ __align__(128) uint4 BfragImg[(size_t)NT * 4 * 32 * 8];
__device__ float sqg[NPTS];

__device__ __forceinline__ float sqrt_approx(float v) {
    float r; asm("sqrt.approx.f32 %0, %1;" : "=f"(r) : "f"(v)); return r;
}
__device__ __forceinline__ float dist_val(float si, float sj, float dot) {
    return sqrt_approx(fmaxf(fmaf(-2.0f, dot, si + sj), 0.0f));
}
__device__ __forceinline__ uint32_t smem_u32(const void* p) {
    return (uint32_t)__cvta_generic_to_shared(p);
}
__device__ __forceinline__ void ldmatrix_x4(uint32_t* r, uint32_t addr) {
    asm volatile("ldmatrix.sync.aligned.m8n8.x4.shared.b16 {%0,%1,%2,%3}, [%4];"
                 : "=r"(r[0]), "=r"(r[1]), "=r"(r[2]), "=r"(r[3]) : "r"(addr));
}
__device__ __forceinline__ void mma_bf16(float* c, const uint32_t* a, const uint32_t* b) {
    asm volatile(
        "mma.sync.aligned.m16n8k16.row.col.f32.bf16.bf16.f32 "
        "{%0,%1,%2,%3}, {%4,%5,%6,%7}, {%8,%9}, {%0,%1,%2,%3};"
        : "+f"(c[0]), "+f"(c[1]), "+f"(c[2]), "+f"(c[3])
        : "r"(a[0]), "r"(a[1]), "r"(a[2]), "r"(a[3]), "r"(b[0]), "r"(b[1]));
}

// 16B store into SW128-swizzled [128][128B] tile
__device__ __forceinline__ void st16_sw(uint8_t* buf, uint32_t off, uint4 v) {
    off ^= (off >> 3) & 0x70;
    *(uint4*)(buf + off) = v;
}

// Convert half a row (16 floats) to hi/lo bf16, store swizzled; return sumsq.
__device__ __forceinline__ float cvt_store(uint8_t* __restrict__ buf, int row,
                                           int half, const float4* __restrict__ src)
{
    float s = 0.0f;
    uint32_t H[8], L[8];
#pragma unroll
    for (int q = 0; q < 4; q++) {
        float4 v = src[q];
        s = fmaf(v.x, v.x, s); s = fmaf(v.y, v.y, s);
        s = fmaf(v.z, v.z, s); s = fmaf(v.w, v.w, s);
        __nv_bfloat16 hx = __float2bfloat16_rn(v.x);
        __nv_bfloat16 hy = __float2bfloat16_rn(v.y);
        __nv_bfloat16 hz = __float2bfloat16_rn(v.z);
        __nv_bfloat16 hw = __float2bfloat16_rn(v.w);
        __nv_bfloat162 h01 = __halves2bfloat162(hx, hy);
        __nv_bfloat162 h23 = __halves2bfloat162(hz, hw);
        __nv_bfloat162 l01 = __floats2bfloat162_rn(v.x - __bfloat162float(hx),
                                                   v.y - __bfloat162float(hy));
        __nv_bfloat162 l23 = __floats2bfloat162_rn(v.z - __bfloat162float(hz),
                                                   v.w - __bfloat162float(hw));
        H[q * 2 + 0] = *(uint32_t*)&h01; H[q * 2 + 1] = *(uint32_t*)&h23;
        L[q * 2 + 0] = *(uint32_t*)&l01; L[q * 2 + 1] = *(uint32_t*)&l23;
    }
    uint32_t base = (uint32_t)row * 128 + (uint32_t)half * 32;
    st16_sw(buf, base +  0, make_uint4(H[0], H[1], H[2], H[3]));
    st16_sw(buf, base + 16, make_uint4(H[4], H[5], H[6], H[7]));
    st16_sw(buf, base + 64, make_uint4(L[0], L[1], L[2], L[3]));
    st16_sw(buf, base + 80, make_uint4(L[4], L[5], L[6], L[7]));
    return s;
}

// ------------- prep: one CTA per 128-row tile, builds fragment images -------
__global__ void __launch_bounds__(256)
prep_frag_kernel(const float* __restrict__ x)
{
    __shared__ __align__(128) uint8_t Abuf[128 * 128];
    __shared__ __align__(128) uint8_t Bbuf[128 * 128];

    const int tile = blockIdx.x;
    const int base = tile << 7;
    const int t    = threadIdx.x;
    const int lane = t & 31;
    const int wid  = t >> 5;

    // load + convert (A layout; B with epilogue row permutation)
    {
        const int row  = t >> 1;
        const int half = t & 1;
        const int v = row & 15, w = v >> 1, r = v & 1;
        const int srowB = (row & ~15) | ((w & 1) << 3) | ((w >> 1) << 1) | r;
        const float4* xr = (const float4*)(x + ((size_t)(base + row) << 5)) + half * 4;
        float s = cvt_store(Abuf, row, half, xr);
        // same source data, permuted row slot for B
        const float4* xr2 = xr;
        cvt_store(Bbuf, srowB, half, xr2);
        s += __shfl_xor_sync(0xFFFFFFFFu, s, 1);
        if (!half) sqg[base + row] = s;
    }
    __syncthreads();

    const uint32_t xmask = (uint32_t)(lane & 7) << 4;

    if (wid < 2) {
        // A fragments for wr = wid
        const int wr = wid;
        const uint32_t aBase  = smem_u32(Abuf) + (uint32_t)(wr * 64 + (lane & 15)) * 128;
        const uint32_t aKhalf = (uint32_t)(lane >> 4) << 4;
        uint4* dst = &AfragImg[(((size_t)tile * 2 + wr) * 32 + lane) * 16];
#pragma unroll
        for (int ks = 0; ks < 2; ks++) {
            const uint32_t off = (uint32_t)(ks * 32) + aKhalf;
#pragma unroll
            for (int mt = 0; mt < 4; mt++) {
                uint32_t fh[4], fl[4];
                ldmatrix_x4(fh, aBase + (uint32_t)mt * 2048 + (off ^ xmask));
                ldmatrix_x4(fl, aBase + (uint32_t)mt * 2048 + ((off + 64) ^ xmask));
                dst[ks * 8 + mt]     = make_uint4(fh[0], fh[1], fh[2], fh[3]);
                dst[ks * 8 + 4 + mt] = make_uint4(fl[0], fl[1], fl[2], fl[3]);
            }
        }
    } else if (wid < 6) {
        // B fragments for wc = wid - 2
        const int wc = wid - 2;
        const uint32_t bBase = smem_u32(Bbuf) +
            (uint32_t)(wc * 32 + ((lane >> 4) << 3) + (lane & 7)) * 128;
        const uint32_t bKhalf = (uint32_t)((lane >> 3) & 1) << 4;
        uint4* dst = &BfragImg[(((size_t)tile * 4 + wc) * 32 + lane) * 8];
#pragma unroll
        for (int ks = 0; ks < 2; ks++) {
            const uint32_t off = (uint32_t)(ks * 32) + bKhalf;
#pragma unroll
            for (int u = 0; u < 2; u++) {
                uint32_t fh[4], fl[4];
                ldmatrix_x4(fh, bBase + (uint32_t)u * 2048 + (off ^ xmask));
                ldmatrix_x4(fl, bBase + (uint32_t)u * 2048 + ((off + 64) ^ xmask));
                dst[ks * 4 + u]     = make_uint4(fh[0], fh[1], fh[2], fh[3]);
                dst[ks * 4 + 2 + u] = make_uint4(fl[0], fl[1], fl[2], fl[3]);
            }
        }
    }
}

// ------------- main: barrier-free LDG-fragments -> HMMA -> STG --------------
__global__ void __launch_bounds__(256, 2)
cdist_frag_kernel(float* __restrict__ out)
{
    const int t    = threadIdx.x;
    const int lane = t & 31;
    const int wid  = t >> 5;
    const int wr   = wid >> 2;
    const int wc   = wid & 3;
    const int a0   = blockIdx.y << 7;
    const int b0   = blockIdx.x << 7;

    const uint4* __restrict__ Af =
        &AfragImg[(((size_t)blockIdx.y * 2 + wr) * 32 + lane) * 16];
    const uint4* __restrict__ Bf =
        &BfragImg[(((size_t)blockIdx.x * 4 + wc) * 32 + lane) * 8];

    float acc[4][4][4];
#pragma unroll
    for (int mt = 0; mt < 4; mt++)
#pragma unroll
        for (int nt = 0; nt < 4; nt++)
#pragma unroll
            for (int i = 0; i < 4; i++) acc[mt][nt][i] = 0.0f;

#pragma unroll
    for (int ks = 0; ks < 2; ks++) {
        uint4 AH[4], BH[2], BL[2];
#pragma unroll
        for (int mt = 0; mt < 4; mt++) AH[mt] = __ldg(Af + ks * 8 + mt);
#pragma unroll
        for (int u = 0; u < 2; u++)    BH[u]  = __ldg(Bf + ks * 4 + u);
#pragma unroll
        for (int u = 0; u < 2; u++)    BL[u]  = __ldg(Bf + ks * 4 + 2 + u);

        // hi . hi
#pragma unroll
        for (int mt = 0; mt < 4; mt++)
#pragma unroll
            for (int nt = 0; nt < 4; nt++)
                mma_bf16(acc[mt][nt], (const uint32_t*)&AH[mt],
                         (const uint32_t*)&BH[nt >> 1] + (nt & 1) * 2);
        // hi . lo
#pragma unroll
        for (int mt = 0; mt < 4; mt++)
#pragma unroll
            for (int nt = 0; nt < 4; nt++)
                mma_bf16(acc[mt][nt], (const uint32_t*)&AH[mt],
                         (const uint32_t*)&BL[nt >> 1] + (nt & 1) * 2);
        // lo . hi (stream A-lo one mt at a time)
#pragma unroll
        for (int mt = 0; mt < 4; mt++) {
            uint4 AL = __ldg(Af + ks * 8 + 4 + mt);
#pragma unroll
            for (int nt = 0; nt < 4; nt++)
                mma_bf16(acc[mt][nt], (const uint32_t*)&AL,
                         (const uint32_t*)&BH[nt >> 1] + (nt & 1) * 2);
        }
    }

    // ---- epilogue: STG.128, sq from global (L1/L2-hot) ----
    const int q  = lane & 3;
    const int gr = lane >> 2;
    const bool diag = (a0 == b0);
    const int cl0 = wc * 32 + q * 4;
    const float4 sjA = __ldg((const float4*)(sqg + b0 + cl0));
    const float4 sjB = __ldg((const float4*)(sqg + b0 + cl0 + 16));
#pragma unroll
    for (int mt = 0; mt < 4; mt++) {
        const int r0l = wr * 64 + mt * 16 + gr;
        const int r1l = r0l + 8;
        const int g0 = a0 + r0l, g1 = a0 + r1l;
        const float si0 = __ldg(sqg + g0);
        const float si1 = __ldg(sqg + g1);
        float* __restrict__ o0 = out + ((size_t)g0 << 14);
        float* __restrict__ o1 = out + ((size_t)g1 << 14);
#pragma unroll
        for (int u = 0; u < 2; u++) {
            const int gc = b0 + cl0 + u * 16;
            const float4 sj = u ? sjB : sjA;
            const float* p0 = acc[mt][2 * u];
            const float* p1 = acc[mt][2 * u + 1];
            float4 w0, w1;
            w0.x = dist_val(si0, sj.x, p0[0]);
            w0.y = dist_val(si0, sj.y, p0[1]);
            w0.z = dist_val(si0, sj.z, p1[0]);
            w0.w = dist_val(si0, sj.w, p1[1]);
            w1.x = dist_val(si1, sj.x, p0[2]);
            w1.y = dist_val(si1, sj.y, p0[3]);
            w1.z = dist_val(si1, sj.z, p1[2]);
            w1.w = dist_val(si1, sj.w, p1[3]);
            if (diag) {
                const int d0 = g0 - gc;
                if (d0 >= 0 && d0 < 4) ((float*)&w0)[d0] = 0.0f;
                const int d1 = g1 - gc;
                if (d1 >= 0 && d1 < 4) ((float*)&w1)[d1] = 0.0f;
            }
            *(float4*)(o0 + gc) = w0;
            *(float4*)(o1 + gc) = w1;
        }
    }
}

extern "C" void kernel_launch(void* const* d_in, const int* in_sizes, int n_in,
                              void* d_out, int out_size)
{
    (void)in_sizes; (void)n_in; (void)out_size;
    const float* x = (const float*)d_in[0];
    float* out = (float*)d_out;
    prep_frag_kernel<<<NT, 256>>>(x);
    dim3 grid(NT, NT);
    cdist_frag_kernel<<<grid, 256>>>(out);
}

// round 8
// speedup vs baseline: 1.8970x; 1.8970x over previous
#include <cuda_runtime.h>
#include <stdint.h>

// cdist: out[i,j] = sqrt(max(||xi||^2 + ||xj||^2 - 2*dot(xi,xj), 0))
// R8: dot via single-pass TF32 mma.sync.m16n8k8 (inputs rounded with
// cvt.rna.tf32.f32). R4 skeleton: 128x128 tile/CTA, 256 thr, 8 warps (2x4),
// warp tile 64x32, SW128-swizzled smem, ldmatrix, permuted-B STG.128 epilogue.

#define NPTS 16384

__device__ __forceinline__ float sqrt_approx(float v) {
    float r; asm("sqrt.approx.f32 %0, %1;" : "=f"(r) : "f"(v)); return r;
}
__device__ __forceinline__ float dist_val(float si, float sj, float dot) {
    return sqrt_approx(fmaxf(fmaf(-2.0f, dot, si + sj), 0.0f));
}
__device__ __forceinline__ uint32_t smem_u32(const void* p) {
    return (uint32_t)__cvta_generic_to_shared(p);
}
__device__ __forceinline__ uint32_t tf32_rna(float f) {
    uint32_t u; asm("cvt.rna.tf32.f32 %0, %1;" : "=r"(u) : "f"(f)); return u;
}
__device__ __forceinline__ void ldmatrix_x4(uint32_t* r, uint32_t addr) {
    asm volatile("ldmatrix.sync.aligned.m8n8.x4.shared.b16 {%0,%1,%2,%3}, [%4];"
                 : "=r"(r[0]), "=r"(r[1]), "=r"(r[2]), "=r"(r[3]) : "r"(addr));
}
__device__ __forceinline__ void mma_tf32(float* c, const uint32_t* a,
                                         uint32_t b0, uint32_t b1) {
    asm volatile(
        "mma.sync.aligned.m16n8k8.row.col.f32.tf32.tf32.f32 "
        "{%0,%1,%2,%3}, {%4,%5,%6,%7}, {%8,%9}, {%0,%1,%2,%3};"
        : "+f"(c[0]), "+f"(c[1]), "+f"(c[2]), "+f"(c[3])
        : "r"(a[0]), "r"(a[1]), "r"(a[2]), "r"(a[3]), "r"(b0), "r"(b1));
}

// 16B store into SW128-swizzled [128 rows][128B] tile: chunk c of row r lands
// at r*128 + ((c ^ (r&7))*16).
__device__ __forceinline__ void st16_sw(uint8_t* buf, int row, int chunk, uint4 v) {
    *(uint4*)(buf + row * 128 + (((uint32_t)chunk ^ (row & 7)) << 4)) = v;
}

// Convert half a row (16 floats) to tf32-rounded fp32, store swizzled; return sumsq.
__device__ __forceinline__ float cvt_store(uint8_t* __restrict__ buf, int row,
                                           int half, const float4* __restrict__ src)
{
    float s = 0.0f;
#pragma unroll
    for (int q = 0; q < 4; q++) {
        float4 v = src[q];
        s = fmaf(v.x, v.x, s); s = fmaf(v.y, v.y, s);
        s = fmaf(v.z, v.z, s); s = fmaf(v.w, v.w, s);
        uint4 w = make_uint4(tf32_rna(v.x), tf32_rna(v.y),
                             tf32_rna(v.z), tf32_rna(v.w));
        st16_sw(buf, row, half * 4 + q, w);
    }
    return s;
}

__global__ void __launch_bounds__(256, 2)
cdist_tf32_kernel(const float* __restrict__ x, float* __restrict__ out)
{
    __shared__ __align__(128) uint8_t Abuf[128 * 128];
    __shared__ __align__(128) uint8_t Bbuf[128 * 128];
    __shared__ float sqa[128];
    __shared__ float sqb[128];

    const int t    = threadIdx.x;
    const int lane = t & 31;
    const int wid  = t >> 5;
    const int a0   = blockIdx.y << 7;
    const int b0   = blockIdx.x << 7;

    // ---- load + tf32-round (thread t: row t/2, half t&1) ----
    // B rows permuted within each 16-group (STG.128 epilogue permutation):
    //   invperm (global v -> smem slot): ((w&1)<<3)|((w>>1)<<1)|r, w=(v&15)>>1, r=v&1
    {
        const int row  = t >> 1;
        const int half = t & 1;
        const int v = row & 15, w = v >> 1, r = v & 1;
        const int srowB = (row & ~15) | ((w & 1) << 3) | ((w >> 1) << 1) | r;
        const float4* xa = (const float4*)(x + ((size_t)(a0 + row) << 5)) + half * 4;
        const float4* xb = (const float4*)(x + ((size_t)(b0 + row) << 5)) + half * 4;
        float sa = cvt_store(Abuf, row,   half, xa);
        float sb = cvt_store(Bbuf, srowB, half, xb);
        sa += __shfl_xor_sync(0xFFFFFFFFu, sa, 1);
        sb += __shfl_xor_sync(0xFFFFFFFFu, sb, 1);
        if (!half) { sqa[row] = sa; sqb[row] = sb; }
    }
    __syncthreads();

    // ---- warp GEMM: warp tile 64x32, 4 k-steps of k8 ----
    const int wr = wid >> 2;
    const int wc = wid & 3;
    const uint32_t lx = (uint32_t)(lane & 7);   // row&7 for both A and B addresses

    // A x4 (per m-tile, per k-step): lane l -> row wr*64 + mt*16 + (l&7) + 8*((l>>3)&1),
    //                                chunk 2ks + (l>>4)
    const uint32_t aRow  = (uint32_t)(wr * 64) + lx + (((uint32_t)(lane >> 3) & 1) << 3);
    const uint32_t aBase = smem_u32(Abuf) + aRow * 128;
    const uint32_t aCsel = (uint32_t)(lane >> 4);          // 0..1
    // B x4 (per n-tile, per k-PAIR): lane l -> row wc*32 + nt*8 + (l&7),
    //                                chunk 4kp + (l>>3)
    const uint32_t bRow  = (uint32_t)(wc * 32) + lx;
    const uint32_t bBase = smem_u32(Bbuf) + bRow * 128;
    const uint32_t bCsel = (uint32_t)(lane >> 3);          // 0..3

    float acc[4][4][4];
#pragma unroll
    for (int mt = 0; mt < 4; mt++)
#pragma unroll
        for (int nt = 0; nt < 4; nt++)
#pragma unroll
            for (int i = 0; i < 4; i++) acc[mt][nt][i] = 0.0f;

#pragma unroll
    for (int kp = 0; kp < 2; kp++) {
        // B frags for 2 k-steps: regs {b0_ks0, b1_ks0, b0_ks1, b1_ks1}
        uint32_t bp[4][4];
        const uint32_t bCh = (((uint32_t)(4 * kp) + bCsel) ^ lx) << 4;
#pragma unroll
        for (int nt = 0; nt < 4; nt++)
            ldmatrix_x4(bp[nt], bBase + (uint32_t)nt * 1024 + bCh);

#pragma unroll
        for (int k2 = 0; k2 < 2; k2++) {
            const int ks = 2 * kp + k2;
            const uint32_t aCh = (((uint32_t)(2 * ks) + aCsel) ^ lx) << 4;
            uint32_t af[4][4];
#pragma unroll
            for (int mt = 0; mt < 4; mt++)
                ldmatrix_x4(af[mt], aBase + (uint32_t)mt * 2048 + aCh);
#pragma unroll
            for (int mt = 0; mt < 4; mt++)
#pragma unroll
                for (int nt = 0; nt < 4; nt++)
                    mma_tf32(acc[mt][nt], af[mt],
                             bp[nt][2 * k2], bp[nt][2 * k2 + 1]);
        }
    }

    // ---- epilogue: STG.128, 4 contiguous global cols per thread ----
    const int q  = lane & 3;
    const int gr = lane >> 2;
    const bool diag = (a0 == b0);
#pragma unroll
    for (int mt = 0; mt < 4; mt++) {
        const int r0l = wr * 64 + mt * 16 + gr;
        const int r1l = r0l + 8;
        const float si0 = sqa[r0l], si1 = sqa[r1l];
        const int g0 = a0 + r0l, g1 = a0 + r1l;
        float* __restrict__ o0 = out + ((size_t)g0 << 14);
        float* __restrict__ o1 = out + ((size_t)g1 << 14);
#pragma unroll
        for (int u = 0; u < 2; u++) {
            const int cl = wc * 32 + u * 16 + q * 4;   // global col (tile-local)
            const int gc = b0 + cl;
            const float4 sj = *(const float4*)&sqb[cl];
            const float* p0 = acc[mt][2 * u];       // smem cols 2q,2q+1 -> g 4q,4q+1
            const float* p1 = acc[mt][2 * u + 1];   // smem cols 8+2q,+1 -> g 4q+2,4q+3
            float4 w0, w1;
            w0.x = dist_val(si0, sj.x, p0[0]);
            w0.y = dist_val(si0, sj.y, p0[1]);
            w0.z = dist_val(si0, sj.z, p1[0]);
            w0.w = dist_val(si0, sj.w, p1[1]);
            w1.x = dist_val(si1, sj.x, p0[2]);
            w1.y = dist_val(si1, sj.y, p0[3]);
            w1.z = dist_val(si1, sj.z, p1[2]);
            w1.w = dist_val(si1, sj.w, p1[3]);
            if (diag) {
                const int d0 = g0 - gc;
                if (d0 >= 0 && d0 < 4) ((float*)&w0)[d0] = 0.0f;
                const int d1 = g1 - gc;
                if (d1 >= 0 && d1 < 4) ((float*)&w1)[d1] = 0.0f;
            }
            *(float4*)(o0 + gc) = w0;
            *(float4*)(o1 + gc) = w1;
        }
    }
}

extern "C" void kernel_launch(void* const* d_in, const int* in_sizes, int n_in,
                              void* d_out, int out_size)
{
    (void)in_sizes; (void)n_in; (void)out_size;
    const float* x = (const float*)d_in[0];
    float* out = (float*)d_out;
    dim3 grid(NPTS / 128, NPTS / 128);
    cdist_tf32_kernel<<<grid, 256>>>(x, out);
}